// round 16
// baseline (speedup 1.0000x reference)
#include <cuda_runtime.h>
#include <math.h>

#define NA 100000
#define NP 200000
#define NE 1000000
#define HIDC 128
#define HEADS 4
#define OUTC 64
#define NEGS 0.2f
#define NDST (2 * NP + NA)     // 500000 concatenated dst slots

typedef unsigned long long u64;

// ---------------- device scratch (allocation-free) ----------------
__device__ float g_h_a[(size_t)NA * HIDC];
__device__ float g_h_p[(size_t)NP * HIDC];
__device__ float g_as_writes[NA * HEADS];
__device__ float g_ad_wb[NA * HEADS];
__device__ float g_ad_writes[NP * HEADS];
__device__ float g_as_wb[NP * HEADS];
__device__ float g_as_cites[NP * HEADS];
__device__ float g_ad_cites[NP * HEADS];
__device__ float g_o_writes[(size_t)NP * HIDC];
__device__ float g_o_wb[(size_t)NA * HIDC];
__device__ float g_o_cites[(size_t)NP * HIDC];
__device__ float g_score[4];
__device__ int   g_is64;
// concatenated CSR: slots [0,NP)=writes->paper, [NP,NP+NA)=wb->author, [NP+NA,NDST)=cites->paper
__device__ int g_cnt[NDST];
__device__ int g_start[NDST];
__device__ int g_pos[NDST];
__device__ int g_aux[512];
__device__ int g_csr[3 * NE];

// ---------------- packed f32x2 helpers ----------------
__device__ __forceinline__ u64 fma2(u64 a, u64 b, u64 c) {
    u64 d; asm("fma.rn.f32x2 %0, %1, %2, %3;" : "=l"(d) : "l"(a), "l"(b), "l"(c)); return d;
}
__device__ __forceinline__ u64 splat2(float x) {
    u64 d; asm("mov.b64 %0, {%1, %1};" : "=l"(d) : "f"(x)); return d;
}
__device__ __forceinline__ float2 unpk(u64 v) {
    float2 r; asm("mov.b64 {%0, %1}, %2;" : "=f"(r.x), "=f"(r.y) : "l"(v)); return r;
}

__device__ __forceinline__ int eidx(const void* p, int e) {
    if (g_is64) return (int)(((const long long*)p)[e]);
    return ((const int*)p)[e];
}

// detect int64 vs int32 edge indices: int64 little-endian => odd dwords all zero
__global__ void detect_kernel(const int* p) {
    int z = 0;
    #pragma unroll
    for (int i = 1; i < 64; i += 2) z |= p[i];
    if (threadIdx.x == 0) g_is64 = (z == 0) ? 1 : 0;
}

// ---------------- fused CSR build over 3 types ----------------
#define EB ((NE + 255) / 256)

__global__ void hist3_kernel(const void* d0, const void* d1, const void* d2, int* cnt) {
    int t = blockIdx.x / EB;
    int e = (blockIdx.x - t * EB) * 256 + threadIdx.x;
    if (e >= NE) return;
    const void* dp = (t == 0) ? d0 : (t == 1) ? d1 : d2;
    int off = (t == 0) ? 0 : (t == 1) ? NP : NP + NA;
    atomicAdd(&cnt[off + eidx(dp, e)], 1);
}

__global__ __launch_bounds__(1024) void scan1_kernel(const int* __restrict__ cnt,
                                                     int* __restrict__ start,
                                                     int* __restrict__ aux, int n) {
    int tid = threadIdx.x;
    int i = blockIdx.x * 1024 + tid;
    int v = (i < n) ? cnt[i] : 0;
    int x = v;
    #pragma unroll
    for (int o = 1; o < 32; o <<= 1) {
        int y = __shfl_up_sync(0xFFFFFFFFu, x, o);
        if ((tid & 31) >= o) x += y;
    }
    __shared__ int ws[32];
    if ((tid & 31) == 31) ws[tid >> 5] = x;
    __syncthreads();
    if (tid < 32) {
        int w = ws[tid];
        #pragma unroll
        for (int o = 1; o < 32; o <<= 1) {
            int y = __shfl_up_sync(0xFFFFFFFFu, w, o);
            if (tid >= o) w += y;
        }
        ws[tid] = w;
    }
    __syncthreads();
    int woff = (tid >= 32) ? ws[(tid >> 5) - 1] : 0;
    if (i < n) start[i] = x - v + woff;
    if (tid == 1023) aux[blockIdx.x] = x + woff;
}

__global__ __launch_bounds__(1024) void scan2_kernel(int* aux, int nb) {
    int tid = threadIdx.x;
    int v = (tid < nb) ? aux[tid] : 0;
    int x = v;
    #pragma unroll
    for (int o = 1; o < 32; o <<= 1) {
        int y = __shfl_up_sync(0xFFFFFFFFu, x, o);
        if ((tid & 31) >= o) x += y;
    }
    __shared__ int ws[32];
    if ((tid & 31) == 31) ws[tid >> 5] = x;
    __syncthreads();
    if (tid < 32) {
        int w = ws[tid];
        #pragma unroll
        for (int o = 1; o < 32; o <<= 1) {
            int y = __shfl_up_sync(0xFFFFFFFFu, w, o);
            if (tid >= o) w += y;
        }
        ws[tid] = w;
    }
    __syncthreads();
    int woff = (tid >= 32) ? ws[(tid >> 5) - 1] : 0;
    if (tid < nb) aux[tid] = x - v + woff;
}

__global__ void scan3_kernel(int* start, const int* __restrict__ aux, int* pos, int n) {
    int i = blockIdx.x * blockDim.x + threadIdx.x;
    if (i < n) {
        int s = start[i] + aux[i >> 10];
        start[i] = s;
        pos[i] = s;
    }
}

__global__ void scatter3_kernel(const void* d0, const void* d1, const void* d2,
                                int* pos, int* csr) {
    int t = blockIdx.x / EB;
    int e = (blockIdx.x - t * EB) * 256 + threadIdx.x;
    if (e >= NE) return;
    const void* dp = (t == 0) ? d0 : (t == 1) ? d1 : d2;
    int off = (t == 0) ? 0 : (t == 1) ? NP : NP + NA;
    int idx = atomicAdd(&pos[off + eidx(dp, e)], 1);
    csr[idx] = e;
}

// ---------------- fused gather: warp per dst over all 500k slots, 2-deep pipeline --------
__global__ __launch_bounds__(256) void gather_kernel(
    const int* __restrict__ csr, const int* __restrict__ start, const int* __restrict__ cnt,
    const void* src0, const void* src1, const void* src2,
    const float* __restrict__ asw, const float* __restrict__ adw,
    const float* __restrict__ aswb, const float* __restrict__ adwb,
    const float* __restrict__ asc, const float* __restrict__ adc,
    const float* __restrict__ Ha, const float* __restrict__ Hp,
    float* __restrict__ ow, float* __restrict__ owb, float* __restrict__ oc)
{
    int g = (blockIdx.x * 256 + threadIdx.x) >> 5;
    if (g >= NDST) return;
    const int lane = threadIdx.x & 31;
    const int head = lane >> 3;

    const void* src; const float* a_s; const float* a_d; const float* H; float* out; int d;
    if (g < NP)            { src = src0; a_s = asw;  a_d = adw;  H = Ha; out = ow;  d = g; }
    else if (g < NP + NA)  { src = src1; a_s = aswb; a_d = adwb; H = Hp; out = owb; d = g - NP; }
    else                   { src = src2; a_s = asc;  a_d = adc;  H = Hp; out = oc;  d = g - NP - NA; }

    const int s0 = start[g];
    const int c = cnt[g];
    const float ad = a_d[d * 4 + head];

    float4 acc = make_float4(0.f, 0.f, 0.f, 0.f);
    float exs = 0.f;

    int s_cur = (c > 0) ? eidx(src, csr[s0]) : 0;
    float as_cur = a_s[s_cur * 4 + head];
    float4 h_cur = ((const float4*)H)[(size_t)s_cur * 32 + lane];

    for (int i = 0; i < c; i++) {
        int s_nxt = (i + 1 < c) ? eidx(src, csr[s0 + i + 1]) : 0;
        float as_nxt = a_s[s_nxt * 4 + head];
        float4 h_nxt = ((const float4*)H)[(size_t)s_nxt * 32 + lane];
        float a = as_cur + ad;
        a = a > 0.f ? a : NEGS * a;
        float w = __expf(a);
        exs += w;
        acc.x += h_cur.x * w; acc.y += h_cur.y * w;
        acc.z += h_cur.z * w; acc.w += h_cur.w * w;
        as_cur = as_nxt; h_cur = h_nxt;
    }
    float inv = 1.f / (exs + 1e-16f);
    ((float4*)out)[(size_t)d * 32 + lane] =
        make_float4(acc.x * inv, acc.y * inv, acc.z * inv, acc.w * inv);
}

// ---------------- fused projection: author blocks then paper blocks ----------------
// 256 threads, 64 nodes/block. cg = tid&31 owns 4 cols; ng = tid>>5 (0..7) owns 4 node-pairs.
#define GA ((NA + 63) / 64)
#define GP ((NP + 63) / 64)

__device__ __forceinline__ void att_one(float4 v, int gn, int N, int cg,
                                        float4 a, float* outp, int head) {
    float p = v.x * a.x + v.y * a.y + v.z * a.z + v.w * a.w;
    p += __shfl_down_sync(0xFFFFFFFFu, p, 4);
    p += __shfl_down_sync(0xFFFFFFFFu, p, 2);
    p += __shfl_down_sync(0xFFFFFFFFu, p, 1);
    if ((cg & 7) == 0 && gn < N) outp[gn * HEADS + head] = p;
}

__global__ __launch_bounds__(256) void proj_kernel(
    const float* __restrict__ Xa, const float* __restrict__ Wa, const float* __restrict__ ba,
    const float* __restrict__ Xp, const float* __restrict__ Wp, const float* __restrict__ bp,
    float* __restrict__ Ha, float* __restrict__ Hp,
    const float* asw, float* p_asw, const float* adwb, float* p_adwb,
    const float* adw, float* p_adw, const float* aswb, float* p_aswb,
    const float* asc, float* p_asc, const float* adc, float* p_adc)
{
    const int isAuthor = (blockIdx.x < GA);
    const float* X; const float* W; const float* b; float* H; int N, node0;
    const float *att0, *att1, *att2, *att3;
    float *out0, *out1, *out2, *out3;
    if (isAuthor) {
        X = Xa; W = Wa; b = ba; H = Ha; N = NA; node0 = blockIdx.x * 64;
        att0 = asw; out0 = p_asw; att1 = adwb; out1 = p_adwb;
        att2 = nullptr; out2 = nullptr; att3 = nullptr; out3 = nullptr;
    } else {
        X = Xp; W = Wp; b = bp; H = Hp; N = NP; node0 = (blockIdx.x - GA) * 64;
        att0 = adw; out0 = p_adw; att1 = aswb; out1 = p_aswb;
        att2 = asc; out2 = p_asc; att3 = adc; out3 = p_adc;
    }

    extern __shared__ float sm[];
    float4* Ws4 = (float4*)sm;                        // 128x128 f32 = 64KB
    u64*    xp  = (u64*)(sm + 16384);                 // 32 pairs x 128 k = 32KB
    const int tid = threadIdx.x;
    const int cg = tid & 31, ng = tid >> 5;

    for (int i = tid; i < 4096; i += 256) Ws4[i] = ((const float4*)W)[i];

    float* xf = (float*)xp;
    for (int i = tid; i < 2048; i += 256) {
        int n = i >> 5, c4 = i & 31, gn = node0 + n;
        float4 v = (gn < N) ? ((const float4*)X)[(size_t)gn * 32 + c4]
                            : make_float4(0.f, 0.f, 0.f, 0.f);
        int base = ((n >> 1) * 128 + c4 * 4) * 2 + (n & 1);
        xf[base] = v.x; xf[base + 2] = v.y; xf[base + 4] = v.z; xf[base + 6] = v.w;
    }
    __syncthreads();

    u64 acc[4][4];
    #pragma unroll
    for (int p = 0; p < 4; p++)
        #pragma unroll
        for (int j = 0; j < 4; j++) acc[p][j] = 0ull;

    const u64* xrow = xp + ng * 4 * 128;
    #pragma unroll 4
    for (int k = 0; k < 128; k++) {
        float4 w = Ws4[k * 32 + cg];
        u64 B0 = splat2(w.x), B1 = splat2(w.y), B2 = splat2(w.z), B3 = splat2(w.w);
        #pragma unroll
        for (int p = 0; p < 4; p++) {
            u64 x2 = xrow[p * 128 + k];
            acc[p][0] = fma2(x2, B0, acc[p][0]);
            acc[p][1] = fma2(x2, B1, acc[p][1]);
            acc[p][2] = fma2(x2, B2, acc[p][2]);
            acc[p][3] = fma2(x2, B3, acc[p][3]);
        }
    }

    float4 b4 = ((const float4*)b)[cg];
    const int head = cg >> 3, d0 = (cg & 7) * 4;
    float4 A0 = make_float4(0,0,0,0), A1 = A0, A2 = A0, A3 = A0;
    if (att0) A0 = *(const float4*)(att0 + head * 32 + d0);
    if (att1) A1 = *(const float4*)(att1 + head * 32 + d0);
    if (att2) A2 = *(const float4*)(att2 + head * 32 + d0);
    if (att3) A3 = *(const float4*)(att3 + head * 32 + d0);

    #pragma unroll
    for (int p = 0; p < 4; p++) {
        float2 c0 = unpk(acc[p][0]), c1 = unpk(acc[p][1]);
        float2 c2 = unpk(acc[p][2]), c3 = unpk(acc[p][3]);
        int n0 = node0 + (ng * 4 + p) * 2;
        float4 ve = make_float4(c0.x + b4.x, c1.x + b4.y, c2.x + b4.z, c3.x + b4.w);
        float4 vo = make_float4(c0.y + b4.x, c1.y + b4.y, c2.y + b4.z, c3.y + b4.w);
        if (n0 < N)     ((float4*)H)[(size_t)n0 * 32 + cg] = ve;
        if (n0 + 1 < N) ((float4*)H)[(size_t)(n0 + 1) * 32 + cg] = vo;
        if (att0) { att_one(ve, n0, N, cg, A0, out0, head); att_one(vo, n0 + 1, N, cg, A0, out0, head); }
        if (att1) { att_one(ve, n0, N, cg, A1, out1, head); att_one(vo, n0 + 1, N, cg, A1, out1, head); }
        if (att2) { att_one(ve, n0, N, cg, A2, out2, head); att_one(vo, n0 + 1, N, cg, A2, out2, head); }
        if (att3) { att_one(ve, n0, N, cg, A3, out3, head); att_one(vo, n0 + 1, N, cg, A3, out3, head); }
    }
}

// ---------------- fused semantic score: one block handles BOTH types for its node tile ----
__global__ __launch_bounds__(256) void score_kernel(
    const float* __restrict__ O0, const float* __restrict__ O1,
    const float* __restrict__ Wk, const float* __restrict__ bk,
    const float* __restrict__ qv, float* scoreBase)
{
    const int node0 = blockIdx.x * 64;
    const int N = NP;

    extern __shared__ float sm[];
    float4* Ws4 = (float4*)sm;
    u64*    xp  = (u64*)(sm + 16384);
    const int tid = threadIdx.x;
    const int cg = tid & 31, ng = tid >> 5;

    for (int i = tid; i < 4096; i += 256) Ws4[i] = ((const float4*)Wk)[i];

    float4 b4 = ((const float4*)bk)[cg];
    float4 q4 = ((const float4*)qv)[cg];
    float* xf = (float*)xp;

    for (int t = 0; t < 2; t++) {
        const float* O = t ? O1 : O0;
        __syncthreads();   // Ws ready (t=0) / prev GEMM + reduction done (t=1)
        for (int i = tid; i < 2048; i += 256) {
            int n = i >> 5, c4 = i & 31, gn = node0 + n;
            float4 v = make_float4(0.f, 0.f, 0.f, 0.f);
            if (gn < N) {
                float4 x = ((const float4*)O)[(size_t)gn * 32 + c4];
                v = make_float4(fmaxf(x.x, 0.f), fmaxf(x.y, 0.f), fmaxf(x.z, 0.f), fmaxf(x.w, 0.f));
            }
            int base = ((n >> 1) * 128 + c4 * 4) * 2 + (n & 1);
            xf[base] = v.x; xf[base + 2] = v.y; xf[base + 4] = v.z; xf[base + 6] = v.w;
        }
        __syncthreads();

        u64 acc[4][4];
        #pragma unroll
        for (int p = 0; p < 4; p++)
            #pragma unroll
            for (int j = 0; j < 4; j++) acc[p][j] = 0ull;

        const u64* xrow = xp + ng * 4 * 128;
        #pragma unroll 4
        for (int k = 0; k < 128; k++) {
            float4 w = Ws4[k * 32 + cg];
            u64 B0 = splat2(w.x), B1 = splat2(w.y), B2 = splat2(w.z), B3 = splat2(w.w);
            #pragma unroll
            for (int p = 0; p < 4; p++) {
                u64 x2 = xrow[p * 128 + k];
                acc[p][0] = fma2(x2, B0, acc[p][0]);
                acc[p][1] = fma2(x2, B1, acc[p][1]);
                acc[p][2] = fma2(x2, B2, acc[p][2]);
                acc[p][3] = fma2(x2, B3, acc[p][3]);
            }
        }

        float s = 0.f;
        #pragma unroll
        for (int p = 0; p < 4; p++) {
            float2 c0 = unpk(acc[p][0]), c1 = unpk(acc[p][1]);
            float2 c2 = unpk(acc[p][2]), c3 = unpk(acc[p][3]);
            int n0 = node0 + (ng * 4 + p) * 2;
            if (n0 < N)
                s += tanhf(c0.x + b4.x) * q4.x + tanhf(c1.x + b4.y) * q4.y
                   + tanhf(c2.x + b4.z) * q4.z + tanhf(c3.x + b4.w) * q4.w;
            if (n0 + 1 < N)
                s += tanhf(c0.y + b4.x) * q4.x + tanhf(c1.y + b4.y) * q4.y
                   + tanhf(c2.y + b4.z) * q4.z + tanhf(c3.y + b4.w) * q4.w;
        }
        #pragma unroll
        for (int o = 16; o > 0; o >>= 1) s += __shfl_down_sync(0xFFFFFFFFu, s, o);
        __syncthreads();   // all warps finished reading xf before we reuse it
        if (cg == 0) xf[ng] = s;
        __syncthreads();
        if (tid == 0) {
            float tot = 0.f;
            #pragma unroll
            for (int i = 0; i < 8; i++) tot += xf[i];
            atomicAdd(scoreBase + t, tot);
        }
    }
}

__global__ void softmax2_kernel(float* score, float invN) {
    if (threadIdx.x == 0 && blockIdx.x == 0) {
        float s0 = score[0] * invN, s1 = score[1] * invN;
        float mx = fmaxf(s0, s1);
        float e0 = expf(s0 - mx), e1 = expf(s1 - mx);
        float inv = 1.f / (e0 + e1);
        score[0] = e0 * inv; score[1] = e1 * inv;
    }
}

// ---------------- final: mode 0 = author (grid GA), mode 1 = paper (grid GP) -------------
__global__ __launch_bounds__(256) void final_kernel(
    const float* __restrict__ Owb, const float* __restrict__ Ow, const float* __restrict__ Oc,
    const float* __restrict__ attn,
    const float* __restrict__ Wl, const float* __restrict__ bl,
    float* __restrict__ outBase, int mode)
{
    const float* O0; const float* O1; float* out; int N, node0;
    float a0, a1;
    if (mode == 0) {
        O0 = Owb; O1 = nullptr; out = outBase; N = NA; node0 = blockIdx.x * 64;
        a0 = 1.f; a1 = 0.f;
    } else {
        O0 = Ow; O1 = Oc; out = outBase + (size_t)NA * OUTC; N = NP;
        node0 = blockIdx.x * 64;
        a0 = attn[0]; a1 = attn[1];
    }

    extern __shared__ float sm[];
    float2* Ws2 = (float2*)sm;                // 128x64 f32 = 32KB
    u64*    xp  = (u64*)(sm + 8192);          // 32 pairs x 128 k = 32KB
    const int tid = threadIdx.x;
    const int cg = tid & 31, ng = tid >> 5;

    for (int i = tid; i < 2048; i += 256) ((float4*)Ws2)[i] = ((const float4*)Wl)[i];

    float* xf = (float*)xp;
    for (int i = tid; i < 2048; i += 256) {
        int n = i >> 5, c4 = i & 31, gn = node0 + n;
        float4 v = make_float4(0.f, 0.f, 0.f, 0.f);
        if (gn < N) {
            float4 x = ((const float4*)O0)[(size_t)gn * 32 + c4];
            v.x = a0 * fmaxf(x.x, 0.f); v.y = a0 * fmaxf(x.y, 0.f);
            v.z = a0 * fmaxf(x.z, 0.f); v.w = a0 * fmaxf(x.w, 0.f);
            if (O1) {
                float4 y = ((const float4*)O1)[(size_t)gn * 32 + c4];
                v.x += a1 * fmaxf(y.x, 0.f); v.y += a1 * fmaxf(y.y, 0.f);
                v.z += a1 * fmaxf(y.z, 0.f); v.w += a1 * fmaxf(y.w, 0.f);
            }
        }
        int base = ((n >> 1) * 128 + c4 * 4) * 2 + (n & 1);
        xf[base] = v.x; xf[base + 2] = v.y; xf[base + 4] = v.z; xf[base + 6] = v.w;
    }
    __syncthreads();

    u64 acc[4][2];
    #pragma unroll
    for (int p = 0; p < 4; p++) { acc[p][0] = 0ull; acc[p][1] = 0ull; }

    const u64* xrow = xp + ng * 4 * 128;
    #pragma unroll 4
    for (int k = 0; k < 128; k++) {
        float2 w = Ws2[k * 32 + cg];
        u64 B0 = splat2(w.x), B1 = splat2(w.y);
        #pragma unroll
        for (int p = 0; p < 4; p++) {
            u64 x2 = xrow[p * 128 + k];
            acc[p][0] = fma2(x2, B0, acc[p][0]);
            acc[p][1] = fma2(x2, B1, acc[p][1]);
        }
    }

    float2 b2 = ((const float2*)bl)[cg];
    #pragma unroll
    for (int p = 0; p < 4; p++) {
        float2 c0 = unpk(acc[p][0]), c1 = unpk(acc[p][1]);
        int n0 = node0 + (ng * 4 + p) * 2;
        if (n0 < N)
            ((float2*)out)[(size_t)n0 * 32 + cg] = make_float2(c0.x + b2.x, c1.x + b2.y);
        if (n0 + 1 < N)
            ((float2*)out)[(size_t)(n0 + 1) * 32 + cg] = make_float2(c0.y + b2.x, c1.y + b2.y);
    }
}

// ---------------- host ----------------
extern "C" void kernel_launch(void* const* d_in, const int* in_sizes, int n_in,
                              void* d_out, int out_size)
{
    (void)in_sizes; (void)n_in; (void)out_size;
    const float* x_a  = (const float*)d_in[0];
    const float* x_p  = (const float*)d_in[1];
    const void*  wr_s = d_in[2];  const void* wr_d = d_in[3];
    const void*  wb_s = d_in[4];  const void* wb_d = d_in[5];
    const void*  ci_s = d_in[6];  const void* ci_d = d_in[7];
    const float* Wpa  = (const float*)d_in[8];  const float* bpa = (const float*)d_in[9];
    const float* Wpp  = (const float*)d_in[10]; const float* bpp = (const float*)d_in[11];
    const float* as_w = (const float*)d_in[12]; const float* ad_w = (const float*)d_in[13];
    const float* as_b = (const float*)d_in[14]; const float* ad_b = (const float*)d_in[15];
    const float* as_c = (const float*)d_in[16]; const float* ad_c = (const float*)d_in[17];
    const float* Wk   = (const float*)d_in[18]; const float* bk   = (const float*)d_in[19];
    const float* qv   = (const float*)d_in[20];
    const float* Wl   = (const float*)d_in[21]; const float* bl   = (const float*)d_in[22];
    float* out = (float*)d_out;

    float *p_h_a, *p_h_p, *p_asw, *p_adwb, *p_adw, *p_aswb, *p_asc, *p_adc;
    float *p_ow, *p_owb, *p_oc, *p_score;
    int *p_cnt, *p_start, *p_pos, *p_aux, *p_csr;
    cudaGetSymbolAddress((void**)&p_h_a,  g_h_a);
    cudaGetSymbolAddress((void**)&p_h_p,  g_h_p);
    cudaGetSymbolAddress((void**)&p_asw,  g_as_writes);
    cudaGetSymbolAddress((void**)&p_adwb, g_ad_wb);
    cudaGetSymbolAddress((void**)&p_adw,  g_ad_writes);
    cudaGetSymbolAddress((void**)&p_aswb, g_as_wb);
    cudaGetSymbolAddress((void**)&p_asc,  g_as_cites);
    cudaGetSymbolAddress((void**)&p_adc,  g_ad_cites);
    cudaGetSymbolAddress((void**)&p_ow,   g_o_writes);
    cudaGetSymbolAddress((void**)&p_owb,  g_o_wb);
    cudaGetSymbolAddress((void**)&p_oc,   g_o_cites);
    cudaGetSymbolAddress((void**)&p_score, g_score);
    cudaGetSymbolAddress((void**)&p_cnt,   g_cnt);
    cudaGetSymbolAddress((void**)&p_start, g_start);
    cudaGetSymbolAddress((void**)&p_pos,   g_pos);
    cudaGetSymbolAddress((void**)&p_aux,   g_aux);
    cudaGetSymbolAddress((void**)&p_csr,   g_csr);

    cudaFuncSetAttribute(proj_kernel,  cudaFuncAttributeMaxDynamicSharedMemorySize, 98304);
    cudaFuncSetAttribute(score_kernel, cudaFuncAttributeMaxDynamicSharedMemorySize, 98304);
    cudaFuncSetAttribute(final_kernel, cudaFuncAttributeMaxDynamicSharedMemorySize, 65536);

    // lazily-created side stream + events (created on the uncaptured correctness
    // run; reused as capture fork/join points afterwards)
    static cudaStream_t s2 = nullptr;
    static cudaEvent_t evFork = nullptr, evCsr = nullptr, evGather = nullptr, evFA = nullptr;
    if (!s2) {
        cudaStreamCreateWithFlags(&s2, cudaStreamNonBlocking);
        cudaEventCreateWithFlags(&evFork,   cudaEventDisableTiming);
        cudaEventCreateWithFlags(&evCsr,    cudaEventDisableTiming);
        cudaEventCreateWithFlags(&evGather, cudaEventDisableTiming);
        cudaEventCreateWithFlags(&evFA,     cudaEventDisableTiming);
    }

    const int NB = (NDST + 1023) / 1024;   // 489 scan blocks

    // ---- main stream: detect, then fork CSR chain to s2 ----
    detect_kernel<<<1, 32>>>((const int*)wr_s);
    cudaEventRecord(evFork, 0);
    cudaMemsetAsync(p_score, 0, 4 * sizeof(float));

    // ---- side stream: CSR build (independent of proj) ----
    cudaStreamWaitEvent(s2, evFork, 0);
    cudaMemsetAsync(p_cnt, 0, (size_t)NDST * sizeof(int), s2);
    hist3_kernel<<<3 * EB, 256, 0, s2>>>(wr_d, wb_d, ci_d, p_cnt);
    scan1_kernel<<<NB, 1024, 0, s2>>>(p_cnt, p_start, p_aux, NDST);
    scan2_kernel<<<1, 1024, 0, s2>>>(p_aux, NB);
    scan3_kernel<<<(NDST + 255) / 256, 256, 0, s2>>>(p_start, p_aux, p_pos, NDST);
    scatter3_kernel<<<3 * EB, 256, 0, s2>>>(wr_d, wb_d, ci_d, p_pos, p_csr);
    cudaEventRecord(evCsr, s2);

    // ---- main stream: projections overlap the CSR build ----
    proj_kernel<<<GA + GP, 256, 98304>>>(
        x_a, Wpa, bpa, x_p, Wpp, bpp, p_h_a, p_h_p,
        as_w, p_asw, ad_b, p_adwb,
        ad_w, p_adw, as_b, p_aswb, as_c, p_asc, ad_c, p_adc);

    // ---- join, then gather ----
    cudaStreamWaitEvent(0, evCsr, 0);
    gather_kernel<<<(NDST * 32 + 255) / 256, 256>>>(
        p_csr, p_start, p_cnt, wr_s, wb_s, ci_s,
        p_asw, p_adw, p_aswb, p_adwb, p_asc, p_adc,
        p_h_a, p_h_p, p_ow, p_owb, p_oc);
    cudaEventRecord(evGather, 0);

    // ---- side stream: author final (independent of score chain) ----
    cudaStreamWaitEvent(s2, evGather, 0);
    final_kernel<<<GA, 256, 65536, s2>>>(p_owb, p_ow, p_oc, p_score, Wl, bl, out, 0);
    cudaEventRecord(evFA, s2);

    // ---- main stream: score -> softmax -> paper final ----
    score_kernel<<<GP, 256, 98304>>>(p_ow, p_oc, Wk, bk, qv, p_score);
    softmax2_kernel<<<1, 32>>>(p_score, 1.f / (float)NP);
    final_kernel<<<GP, 256, 65536>>>(p_owb, p_ow, p_oc, p_score, Wl, bl, out, 1);

    // ---- join author final back before returning ----
    cudaStreamWaitEvent(0, evFA, 0);
}

// round 17
// speedup vs baseline: 1.0002x; 1.0002x over previous
#include <cuda_runtime.h>
#include <math.h>

#define NA 100000
#define NP 200000
#define NE 1000000
#define HIDC 128
#define HEADS 4
#define OUTC 64
#define NEGS 0.2f
#define NDST (2 * NP + NA)     // 500000 concatenated dst slots

typedef unsigned long long u64;

// ---------------- device scratch (allocation-free) ----------------
__device__ float g_h_a[(size_t)NA * HIDC];
__device__ float g_h_p[(size_t)NP * HIDC];
__device__ float g_as_writes[NA * HEADS];
__device__ float g_ad_wb[NA * HEADS];
__device__ float g_ad_writes[NP * HEADS];
__device__ float g_as_wb[NP * HEADS];
__device__ float g_as_cites[NP * HEADS];
__device__ float g_ad_cites[NP * HEADS];
__device__ float g_o_writes[(size_t)NP * HIDC];
__device__ float g_o_wb[(size_t)NA * HIDC];
__device__ float g_o_cites[(size_t)NP * HIDC];
__device__ float g_score[4];
__device__ int   g_is64;
// concatenated CSR: slots [0,NP)=writes->paper, [NP,NP+NA)=wb->author, [NP+NA,NDST)=cites->paper
__device__ int g_cnt[NDST];
__device__ int g_start[NDST];
__device__ int g_pos[NDST];
__device__ int g_aux[512];
__device__ int g_csr[3 * NE];

// ---------------- packed f32x2 helpers ----------------
__device__ __forceinline__ u64 fma2(u64 a, u64 b, u64 c) {
    u64 d; asm("fma.rn.f32x2 %0, %1, %2, %3;" : "=l"(d) : "l"(a), "l"(b), "l"(c)); return d;
}
__device__ __forceinline__ u64 splat2(float x) {
    u64 d; asm("mov.b64 %0, {%1, %1};" : "=l"(d) : "f"(x)); return d;
}
__device__ __forceinline__ float2 unpk(u64 v) {
    float2 r; asm("mov.b64 {%0, %1}, %2;" : "=f"(r.x), "=f"(r.y) : "l"(v)); return r;
}

__device__ __forceinline__ int eidx(const void* p, int e) {
    if (g_is64) return (int)(((const long long*)p)[e]);
    return ((const int*)p)[e];
}

// detect int64 vs int32 edge indices: int64 little-endian => odd dwords all zero
__global__ void detect_kernel(const int* p) {
    int z = 0;
    #pragma unroll
    for (int i = 1; i < 64; i += 2) z |= p[i];
    if (threadIdx.x == 0) g_is64 = (z == 0) ? 1 : 0;
}

// ---------------- fused CSR build over 3 types ----------------
#define EB ((NE + 255) / 256)

__global__ void hist3_kernel(const void* d0, const void* d1, const void* d2, int* cnt) {
    int t = blockIdx.x / EB;
    int e = (blockIdx.x - t * EB) * 256 + threadIdx.x;
    if (e >= NE) return;
    const void* dp = (t == 0) ? d0 : (t == 1) ? d1 : d2;
    int off = (t == 0) ? 0 : (t == 1) ? NP : NP + NA;
    atomicAdd(&cnt[off + eidx(dp, e)], 1);
}

__global__ __launch_bounds__(1024) void scan1_kernel(const int* __restrict__ cnt,
                                                     int* __restrict__ start,
                                                     int* __restrict__ aux, int n) {
    int tid = threadIdx.x;
    int i = blockIdx.x * 1024 + tid;
    int v = (i < n) ? cnt[i] : 0;
    int x = v;
    #pragma unroll
    for (int o = 1; o < 32; o <<= 1) {
        int y = __shfl_up_sync(0xFFFFFFFFu, x, o);
        if ((tid & 31) >= o) x += y;
    }
    __shared__ int ws[32];
    if ((tid & 31) == 31) ws[tid >> 5] = x;
    __syncthreads();
    if (tid < 32) {
        int w = ws[tid];
        #pragma unroll
        for (int o = 1; o < 32; o <<= 1) {
            int y = __shfl_up_sync(0xFFFFFFFFu, w, o);
            if (tid >= o) w += y;
        }
        ws[tid] = w;
    }
    __syncthreads();
    int woff = (tid >= 32) ? ws[(tid >> 5) - 1] : 0;
    if (i < n) start[i] = x - v + woff;
    if (tid == 1023) aux[blockIdx.x] = x + woff;
}

__global__ __launch_bounds__(1024) void scan2_kernel(int* aux, int nb) {
    int tid = threadIdx.x;
    int v = (tid < nb) ? aux[tid] : 0;
    int x = v;
    #pragma unroll
    for (int o = 1; o < 32; o <<= 1) {
        int y = __shfl_up_sync(0xFFFFFFFFu, x, o);
        if ((tid & 31) >= o) x += y;
    }
    __shared__ int ws[32];
    if ((tid & 31) == 31) ws[tid >> 5] = x;
    __syncthreads();
    if (tid < 32) {
        int w = ws[tid];
        #pragma unroll
        for (int o = 1; o < 32; o <<= 1) {
            int y = __shfl_up_sync(0xFFFFFFFFu, w, o);
            if (tid >= o) w += y;
        }
        ws[tid] = w;
    }
    __syncthreads();
    int woff = (tid >= 32) ? ws[(tid >> 5) - 1] : 0;
    if (tid < nb) aux[tid] = x - v + woff;
}

__global__ void scan3_kernel(int* start, const int* __restrict__ aux, int* pos, int n) {
    int i = blockIdx.x * blockDim.x + threadIdx.x;
    if (i < n) {
        int s = start[i] + aux[i >> 10];
        start[i] = s;
        pos[i] = s;
    }
}

__global__ void scatter3_kernel(const void* d0, const void* d1, const void* d2,
                                int* pos, int* csr) {
    int t = blockIdx.x / EB;
    int e = (blockIdx.x - t * EB) * 256 + threadIdx.x;
    if (e >= NE) return;
    const void* dp = (t == 0) ? d0 : (t == 1) ? d1 : d2;
    int off = (t == 0) ? 0 : (t == 1) ? NP : NP + NA;
    int idx = atomicAdd(&pos[off + eidx(dp, e)], 1);
    csr[idx] = e;
}

// ---------------- fused gather: warp per dst over all 500k slots, 2-deep pipeline --------
__global__ __launch_bounds__(256) void gather_kernel(
    const int* __restrict__ csr, const int* __restrict__ start, const int* __restrict__ cnt,
    const void* src0, const void* src1, const void* src2,
    const float* __restrict__ asw, const float* __restrict__ adw,
    const float* __restrict__ aswb, const float* __restrict__ adwb,
    const float* __restrict__ asc, const float* __restrict__ adc,
    const float* __restrict__ Ha, const float* __restrict__ Hp,
    float* __restrict__ ow, float* __restrict__ owb, float* __restrict__ oc)
{
    int g = (blockIdx.x * 256 + threadIdx.x) >> 5;
    if (g >= NDST) return;
    const int lane = threadIdx.x & 31;
    const int head = lane >> 3;

    const void* src; const float* a_s; const float* a_d; const float* H; float* out; int d;
    if (g < NP)            { src = src0; a_s = asw;  a_d = adw;  H = Ha; out = ow;  d = g; }
    else if (g < NP + NA)  { src = src1; a_s = aswb; a_d = adwb; H = Hp; out = owb; d = g - NP; }
    else                   { src = src2; a_s = asc;  a_d = adc;  H = Hp; out = oc;  d = g - NP - NA; }

    const int s0 = start[g];
    const int c = cnt[g];
    const float ad = a_d[d * 4 + head];

    float4 acc = make_float4(0.f, 0.f, 0.f, 0.f);
    float exs = 0.f;

    int s_cur = (c > 0) ? eidx(src, csr[s0]) : 0;
    float as_cur = a_s[s_cur * 4 + head];
    float4 h_cur = ((const float4*)H)[(size_t)s_cur * 32 + lane];

    for (int i = 0; i < c; i++) {
        int s_nxt = (i + 1 < c) ? eidx(src, csr[s0 + i + 1]) : 0;
        float as_nxt = a_s[s_nxt * 4 + head];
        float4 h_nxt = ((const float4*)H)[(size_t)s_nxt * 32 + lane];
        float a = as_cur + ad;
        a = a > 0.f ? a : NEGS * a;
        float w = __expf(a);
        exs += w;
        acc.x += h_cur.x * w; acc.y += h_cur.y * w;
        acc.z += h_cur.z * w; acc.w += h_cur.w * w;
        as_cur = as_nxt; h_cur = h_nxt;
    }
    float inv = 1.f / (exs + 1e-16f);
    ((float4*)out)[(size_t)d * 32 + lane] =
        make_float4(acc.x * inv, acc.y * inv, acc.z * inv, acc.w * inv);
}

// ---------------- fused projection: author blocks then paper blocks ----------------
// 256 threads, 64 nodes/block. cg = tid&31 owns 4 cols; ng = tid>>5 (0..7) owns 4 node-pairs.
#define GA ((NA + 63) / 64)
#define GP ((NP + 63) / 64)

__device__ __forceinline__ void att_one(float4 v, int gn, int N, int cg,
                                        float4 a, float* outp, int head) {
    float p = v.x * a.x + v.y * a.y + v.z * a.z + v.w * a.w;
    p += __shfl_down_sync(0xFFFFFFFFu, p, 4);
    p += __shfl_down_sync(0xFFFFFFFFu, p, 2);
    p += __shfl_down_sync(0xFFFFFFFFu, p, 1);
    if ((cg & 7) == 0 && gn < N) outp[gn * HEADS + head] = p;
}

__global__ __launch_bounds__(256) void proj_kernel(
    const float* __restrict__ Xa, const float* __restrict__ Wa, const float* __restrict__ ba,
    const float* __restrict__ Xp, const float* __restrict__ Wp, const float* __restrict__ bp,
    float* __restrict__ Ha, float* __restrict__ Hp,
    const float* asw, float* p_asw, const float* adwb, float* p_adwb,
    const float* adw, float* p_adw, const float* aswb, float* p_aswb,
    const float* asc, float* p_asc, const float* adc, float* p_adc)
{
    const int isAuthor = (blockIdx.x < GA);
    const float* X; const float* W; const float* b; float* H; int N, node0;
    const float *att0, *att1, *att2, *att3;
    float *out0, *out1, *out2, *out3;
    if (isAuthor) {
        X = Xa; W = Wa; b = ba; H = Ha; N = NA; node0 = blockIdx.x * 64;
        att0 = asw; out0 = p_asw; att1 = adwb; out1 = p_adwb;
        att2 = nullptr; out2 = nullptr; att3 = nullptr; out3 = nullptr;
    } else {
        X = Xp; W = Wp; b = bp; H = Hp; N = NP; node0 = (blockIdx.x - GA) * 64;
        att0 = adw; out0 = p_adw; att1 = aswb; out1 = p_aswb;
        att2 = asc; out2 = p_asc; att3 = adc; out3 = p_adc;
    }

    extern __shared__ float sm[];
    float4* Ws4 = (float4*)sm;                        // 128x128 f32 = 64KB
    u64*    xp  = (u64*)(sm + 16384);                 // 32 pairs x 128 k = 32KB
    const int tid = threadIdx.x;
    const int cg = tid & 31, ng = tid >> 5;

    for (int i = tid; i < 4096; i += 256) Ws4[i] = ((const float4*)W)[i];

    float* xf = (float*)xp;
    for (int i = tid; i < 2048; i += 256) {
        int n = i >> 5, c4 = i & 31, gn = node0 + n;
        float4 v = (gn < N) ? ((const float4*)X)[(size_t)gn * 32 + c4]
                            : make_float4(0.f, 0.f, 0.f, 0.f);
        int base = ((n >> 1) * 128 + c4 * 4) * 2 + (n & 1);
        xf[base] = v.x; xf[base + 2] = v.y; xf[base + 4] = v.z; xf[base + 6] = v.w;
    }
    __syncthreads();

    u64 acc[4][4];
    #pragma unroll
    for (int p = 0; p < 4; p++)
        #pragma unroll
        for (int j = 0; j < 4; j++) acc[p][j] = 0ull;

    const u64* xrow = xp + ng * 4 * 128;
    #pragma unroll 4
    for (int k = 0; k < 128; k++) {
        float4 w = Ws4[k * 32 + cg];
        u64 B0 = splat2(w.x), B1 = splat2(w.y), B2 = splat2(w.z), B3 = splat2(w.w);
        #pragma unroll
        for (int p = 0; p < 4; p++) {
            u64 x2 = xrow[p * 128 + k];
            acc[p][0] = fma2(x2, B0, acc[p][0]);
            acc[p][1] = fma2(x2, B1, acc[p][1]);
            acc[p][2] = fma2(x2, B2, acc[p][2]);
            acc[p][3] = fma2(x2, B3, acc[p][3]);
        }
    }

    float4 b4 = ((const float4*)b)[cg];
    const int head = cg >> 3, d0 = (cg & 7) * 4;
    float4 A0 = make_float4(0,0,0,0), A1 = A0, A2 = A0, A3 = A0;
    if (att0) A0 = *(const float4*)(att0 + head * 32 + d0);
    if (att1) A1 = *(const float4*)(att1 + head * 32 + d0);
    if (att2) A2 = *(const float4*)(att2 + head * 32 + d0);
    if (att3) A3 = *(const float4*)(att3 + head * 32 + d0);

    #pragma unroll
    for (int p = 0; p < 4; p++) {
        float2 c0 = unpk(acc[p][0]), c1 = unpk(acc[p][1]);
        float2 c2 = unpk(acc[p][2]), c3 = unpk(acc[p][3]);
        int n0 = node0 + (ng * 4 + p) * 2;
        float4 ve = make_float4(c0.x + b4.x, c1.x + b4.y, c2.x + b4.z, c3.x + b4.w);
        float4 vo = make_float4(c0.y + b4.x, c1.y + b4.y, c2.y + b4.z, c3.y + b4.w);
        if (n0 < N)     ((float4*)H)[(size_t)n0 * 32 + cg] = ve;
        if (n0 + 1 < N) ((float4*)H)[(size_t)(n0 + 1) * 32 + cg] = vo;
        if (att0) { att_one(ve, n0, N, cg, A0, out0, head); att_one(vo, n0 + 1, N, cg, A0, out0, head); }
        if (att1) { att_one(ve, n0, N, cg, A1, out1, head); att_one(vo, n0 + 1, N, cg, A1, out1, head); }
        if (att2) { att_one(ve, n0, N, cg, A2, out2, head); att_one(vo, n0 + 1, N, cg, A2, out2, head); }
        if (att3) { att_one(ve, n0, N, cg, A3, out3, head); att_one(vo, n0 + 1, N, cg, A3, out3, head); }
    }
}

// ---------------- fused semantic score: one block handles BOTH types for its node tile ----
__global__ __launch_bounds__(256) void score_kernel(
    const float* __restrict__ O0, const float* __restrict__ O1,
    const float* __restrict__ Wk, const float* __restrict__ bk,
    const float* __restrict__ qv, float* scoreBase)
{
    const int node0 = blockIdx.x * 64;
    const int N = NP;

    extern __shared__ float sm[];
    float4* Ws4 = (float4*)sm;
    u64*    xp  = (u64*)(sm + 16384);
    const int tid = threadIdx.x;
    const int cg = tid & 31, ng = tid >> 5;

    for (int i = tid; i < 4096; i += 256) Ws4[i] = ((const float4*)Wk)[i];

    float4 b4 = ((const float4*)bk)[cg];
    float4 q4 = ((const float4*)qv)[cg];
    float* xf = (float*)xp;

    for (int t = 0; t < 2; t++) {
        const float* O = t ? O1 : O0;
        __syncthreads();   // Ws ready (t=0) / prev GEMM + reduction done (t=1)
        for (int i = tid; i < 2048; i += 256) {
            int n = i >> 5, c4 = i & 31, gn = node0 + n;
            float4 v = make_float4(0.f, 0.f, 0.f, 0.f);
            if (gn < N) {
                float4 x = ((const float4*)O)[(size_t)gn * 32 + c4];
                v = make_float4(fmaxf(x.x, 0.f), fmaxf(x.y, 0.f), fmaxf(x.z, 0.f), fmaxf(x.w, 0.f));
            }
            int base = ((n >> 1) * 128 + c4 * 4) * 2 + (n & 1);
            xf[base] = v.x; xf[base + 2] = v.y; xf[base + 4] = v.z; xf[base + 6] = v.w;
        }
        __syncthreads();

        u64 acc[4][4];
        #pragma unroll
        for (int p = 0; p < 4; p++)
            #pragma unroll
            for (int j = 0; j < 4; j++) acc[p][j] = 0ull;

        const u64* xrow = xp + ng * 4 * 128;
        #pragma unroll 4
        for (int k = 0; k < 128; k++) {
            float4 w = Ws4[k * 32 + cg];
            u64 B0 = splat2(w.x), B1 = splat2(w.y), B2 = splat2(w.z), B3 = splat2(w.w);
            #pragma unroll
            for (int p = 0; p < 4; p++) {
                u64 x2 = xrow[p * 128 + k];
                acc[p][0] = fma2(x2, B0, acc[p][0]);
                acc[p][1] = fma2(x2, B1, acc[p][1]);
                acc[p][2] = fma2(x2, B2, acc[p][2]);
                acc[p][3] = fma2(x2, B3, acc[p][3]);
            }
        }

        float s = 0.f;
        #pragma unroll
        for (int p = 0; p < 4; p++) {
            float2 c0 = unpk(acc[p][0]), c1 = unpk(acc[p][1]);
            float2 c2 = unpk(acc[p][2]), c3 = unpk(acc[p][3]);
            int n0 = node0 + (ng * 4 + p) * 2;
            if (n0 < N)
                s += tanhf(c0.x + b4.x) * q4.x + tanhf(c1.x + b4.y) * q4.y
                   + tanhf(c2.x + b4.z) * q4.z + tanhf(c3.x + b4.w) * q4.w;
            if (n0 + 1 < N)
                s += tanhf(c0.y + b4.x) * q4.x + tanhf(c1.y + b4.y) * q4.y
                   + tanhf(c2.y + b4.z) * q4.z + tanhf(c3.y + b4.w) * q4.w;
        }
        #pragma unroll
        for (int o = 16; o > 0; o >>= 1) s += __shfl_down_sync(0xFFFFFFFFu, s, o);
        __syncthreads();   // all warps finished reading xf before we reuse it
        if (cg == 0) xf[ng] = s;
        __syncthreads();
        if (tid == 0) {
            float tot = 0.f;
            #pragma unroll
            for (int i = 0; i < 8; i++) tot += xf[i];
            atomicAdd(scoreBase + t, tot);
        }
    }
}

__global__ void softmax2_kernel(float* score, float invN) {
    if (threadIdx.x == 0 && blockIdx.x == 0) {
        float s0 = score[0] * invN, s1 = score[1] * invN;
        float mx = fmaxf(s0, s1);
        float e0 = expf(s0 - mx), e1 = expf(s1 - mx);
        float inv = 1.f / (e0 + e1);
        score[0] = e0 * inv; score[1] = e1 * inv;
    }
}

// ---------------- final: mode 0 = author (grid GA), mode 1 = paper (grid GP) -------------
__global__ __launch_bounds__(256) void final_kernel(
    const float* __restrict__ Owb, const float* __restrict__ Ow, const float* __restrict__ Oc,
    const float* __restrict__ attn,
    const float* __restrict__ Wl, const float* __restrict__ bl,
    float* __restrict__ outBase, int mode)
{
    const float* O0; const float* O1; float* out; int N, node0;
    float a0, a1;
    if (mode == 0) {
        O0 = Owb; O1 = nullptr; out = outBase; N = NA; node0 = blockIdx.x * 64;
        a0 = 1.f; a1 = 0.f;
    } else {
        O0 = Ow; O1 = Oc; out = outBase + (size_t)NA * OUTC; N = NP;
        node0 = blockIdx.x * 64;
        a0 = attn[0]; a1 = attn[1];
    }

    extern __shared__ float sm[];
    float2* Ws2 = (float2*)sm;                // 128x64 f32 = 32KB
    u64*    xp  = (u64*)(sm + 8192);          // 32 pairs x 128 k = 32KB
    const int tid = threadIdx.x;
    const int cg = tid & 31, ng = tid >> 5;

    for (int i = tid; i < 2048; i += 256) ((float4*)Ws2)[i] = ((const float4*)Wl)[i];

    float* xf = (float*)xp;
    for (int i = tid; i < 2048; i += 256) {
        int n = i >> 5, c4 = i & 31, gn = node0 + n;
        float4 v = make_float4(0.f, 0.f, 0.f, 0.f);
        if (gn < N) {
            float4 x = ((const float4*)O0)[(size_t)gn * 32 + c4];
            v.x = a0 * fmaxf(x.x, 0.f); v.y = a0 * fmaxf(x.y, 0.f);
            v.z = a0 * fmaxf(x.z, 0.f); v.w = a0 * fmaxf(x.w, 0.f);
            if (O1) {
                float4 y = ((const float4*)O1)[(size_t)gn * 32 + c4];
                v.x += a1 * fmaxf(y.x, 0.f); v.y += a1 * fmaxf(y.y, 0.f);
                v.z += a1 * fmaxf(y.z, 0.f); v.w += a1 * fmaxf(y.w, 0.f);
            }
        }
        int base = ((n >> 1) * 128 + c4 * 4) * 2 + (n & 1);
        xf[base] = v.x; xf[base + 2] = v.y; xf[base + 4] = v.z; xf[base + 6] = v.w;
    }
    __syncthreads();

    u64 acc[4][2];
    #pragma unroll
    for (int p = 0; p < 4; p++) { acc[p][0] = 0ull; acc[p][1] = 0ull; }

    const u64* xrow = xp + ng * 4 * 128;
    #pragma unroll 4
    for (int k = 0; k < 128; k++) {
        float2 w = Ws2[k * 32 + cg];
        u64 B0 = splat2(w.x), B1 = splat2(w.y);
        #pragma unroll
        for (int p = 0; p < 4; p++) {
            u64 x2 = xrow[p * 128 + k];
            acc[p][0] = fma2(x2, B0, acc[p][0]);
            acc[p][1] = fma2(x2, B1, acc[p][1]);
        }
    }

    float2 b2 = ((const float2*)bl)[cg];
    #pragma unroll
    for (int p = 0; p < 4; p++) {
        float2 c0 = unpk(acc[p][0]), c1 = unpk(acc[p][1]);
        int n0 = node0 + (ng * 4 + p) * 2;
        if (n0 < N)
            ((float2*)out)[(size_t)n0 * 32 + cg] = make_float2(c0.x + b2.x, c1.x + b2.y);
        if (n0 + 1 < N)
            ((float2*)out)[(size_t)(n0 + 1) * 32 + cg] = make_float2(c0.y + b2.x, c1.y + b2.y);
    }
}

// ---------------- host ----------------
extern "C" void kernel_launch(void* const* d_in, const int* in_sizes, int n_in,
                              void* d_out, int out_size)
{
    (void)in_sizes; (void)n_in; (void)out_size;
    const float* x_a  = (const float*)d_in[0];
    const float* x_p  = (const float*)d_in[1];
    const void*  wr_s = d_in[2];  const void* wr_d = d_in[3];
    const void*  wb_s = d_in[4];  const void* wb_d = d_in[5];
    const void*  ci_s = d_in[6];  const void* ci_d = d_in[7];
    const float* Wpa  = (const float*)d_in[8];  const float* bpa = (const float*)d_in[9];
    const float* Wpp  = (const float*)d_in[10]; const float* bpp = (const float*)d_in[11];
    const float* as_w = (const float*)d_in[12]; const float* ad_w = (const float*)d_in[13];
    const float* as_b = (const float*)d_in[14]; const float* ad_b = (const float*)d_in[15];
    const float* as_c = (const float*)d_in[16]; const float* ad_c = (const float*)d_in[17];
    const float* Wk   = (const float*)d_in[18]; const float* bk   = (const float*)d_in[19];
    const float* qv   = (const float*)d_in[20];
    const float* Wl   = (const float*)d_in[21]; const float* bl   = (const float*)d_in[22];
    float* out = (float*)d_out;

    float *p_h_a, *p_h_p, *p_asw, *p_adwb, *p_adw, *p_aswb, *p_asc, *p_adc;
    float *p_ow, *p_owb, *p_oc, *p_score;
    int *p_cnt, *p_start, *p_pos, *p_aux, *p_csr;
    cudaGetSymbolAddress((void**)&p_h_a,  g_h_a);
    cudaGetSymbolAddress((void**)&p_h_p,  g_h_p);
    cudaGetSymbolAddress((void**)&p_asw,  g_as_writes);
    cudaGetSymbolAddress((void**)&p_adwb, g_ad_wb);
    cudaGetSymbolAddress((void**)&p_adw,  g_ad_writes);
    cudaGetSymbolAddress((void**)&p_aswb, g_as_wb);
    cudaGetSymbolAddress((void**)&p_asc,  g_as_cites);
    cudaGetSymbolAddress((void**)&p_adc,  g_ad_cites);
    cudaGetSymbolAddress((void**)&p_ow,   g_o_writes);
    cudaGetSymbolAddress((void**)&p_owb,  g_o_wb);
    cudaGetSymbolAddress((void**)&p_oc,   g_o_cites);
    cudaGetSymbolAddress((void**)&p_score, g_score);
    cudaGetSymbolAddress((void**)&p_cnt,   g_cnt);
    cudaGetSymbolAddress((void**)&p_start, g_start);
    cudaGetSymbolAddress((void**)&p_pos,   g_pos);
    cudaGetSymbolAddress((void**)&p_aux,   g_aux);
    cudaGetSymbolAddress((void**)&p_csr,   g_csr);

    cudaFuncSetAttribute(proj_kernel,  cudaFuncAttributeMaxDynamicSharedMemorySize, 98304);
    cudaFuncSetAttribute(score_kernel, cudaFuncAttributeMaxDynamicSharedMemorySize, 98304);
    cudaFuncSetAttribute(final_kernel, cudaFuncAttributeMaxDynamicSharedMemorySize, 65536);

    // lazily-created side stream + events (created on the uncaptured correctness
    // run; reused as capture fork/join points afterwards)
    static cudaStream_t s2 = nullptr;
    static cudaEvent_t evFork = nullptr, evCsr = nullptr, evGather = nullptr, evFA = nullptr;
    if (!s2) {
        cudaStreamCreateWithFlags(&s2, cudaStreamNonBlocking);
        cudaEventCreateWithFlags(&evFork,   cudaEventDisableTiming);
        cudaEventCreateWithFlags(&evCsr,    cudaEventDisableTiming);
        cudaEventCreateWithFlags(&evGather, cudaEventDisableTiming);
        cudaEventCreateWithFlags(&evFA,     cudaEventDisableTiming);
    }

    const int NB = (NDST + 1023) / 1024;   // 489 scan blocks

    // ---- main stream: detect, then fork CSR chain to s2 ----
    detect_kernel<<<1, 32>>>((const int*)wr_s);
    cudaEventRecord(evFork, 0);
    cudaMemsetAsync(p_score, 0, 4 * sizeof(float));

    // ---- side stream: CSR build (independent of proj) ----
    cudaStreamWaitEvent(s2, evFork, 0);
    cudaMemsetAsync(p_cnt, 0, (size_t)NDST * sizeof(int), s2);
    hist3_kernel<<<3 * EB, 256, 0, s2>>>(wr_d, wb_d, ci_d, p_cnt);
    scan1_kernel<<<NB, 1024, 0, s2>>>(p_cnt, p_start, p_aux, NDST);
    scan2_kernel<<<1, 1024, 0, s2>>>(p_aux, NB);
    scan3_kernel<<<(NDST + 255) / 256, 256, 0, s2>>>(p_start, p_aux, p_pos, NDST);
    scatter3_kernel<<<3 * EB, 256, 0, s2>>>(wr_d, wb_d, ci_d, p_pos, p_csr);
    cudaEventRecord(evCsr, s2);

    // ---- main stream: projections overlap the CSR build ----
    proj_kernel<<<GA + GP, 256, 98304>>>(
        x_a, Wpa, bpa, x_p, Wpp, bpp, p_h_a, p_h_p,
        as_w, p_asw, ad_b, p_adwb,
        ad_w, p_adw, as_b, p_aswb, as_c, p_asc, ad_c, p_adc);

    // ---- join, then gather ----
    cudaStreamWaitEvent(0, evCsr, 0);
    gather_kernel<<<(NDST * 32 + 255) / 256, 256>>>(
        p_csr, p_start, p_cnt, wr_s, wb_s, ci_s,
        p_asw, p_adw, p_aswb, p_adwb, p_asc, p_adc,
        p_h_a, p_h_p, p_ow, p_owb, p_oc);
    cudaEventRecord(evGather, 0);

    // ---- side stream: author final (independent of score chain) ----
    cudaStreamWaitEvent(s2, evGather, 0);
    final_kernel<<<GA, 256, 65536, s2>>>(p_owb, p_ow, p_oc, p_score, Wl, bl, out, 0);
    cudaEventRecord(evFA, s2);

    // ---- main stream: score -> softmax -> paper final ----
    score_kernel<<<GP, 256, 98304>>>(p_ow, p_oc, Wk, bk, qv, p_score);
    softmax2_kernel<<<1, 32>>>(p_score, 1.f / (float)NP);
    final_kernel<<<GP, 256, 65536>>>(p_owb, p_ow, p_oc, p_score, Wl, bl, out, 1);

    // ---- join author final back before returning ----
    cudaStreamWaitEvent(0, evFA, 0);
}